// round 3
// baseline (speedup 1.0000x reference)
#include <cuda_runtime.h>
#include <cuda_bf16.h>
#include <cstdint>

#define N_NODES 50000
#define DIM     128
#define E_REAL  200000
#define E_TOT   250000   // + self loops
#define P_EDGES 50000
#define HEADS   4
#define HID     256
#define H1DIM   1024     // HEADS*HID
#define EMB     128
#define SLOPE   0.2f

#define Z_ELEMS   ((size_t)N_NODES * EMB)          // 6.4M
#define LOG_OFF   (Z_ELEMS)                        // logits at 6.4M
#define PRED_OFF  (Z_ELEMS + (size_t)N_NODES * 4)  // preds at 6.6M

// ---------------- scratch (device globals; no allocs allowed) ----------------
__device__ float g_h1  [(size_t)N_NODES * H1DIM];  // layer1 features (pre-agg)
__device__ float g_agg1[(size_t)N_NODES * H1DIM];  // layer1 aggregated -> elu -> layer2 input
__device__ float g_hh2 [(size_t)N_NODES * EMB];    // layer2 features (pre-agg)
__device__ float g_as1 [(size_t)N_NODES * HEADS];
__device__ float g_ad1 [(size_t)N_NODES * HEADS];
__device__ float g_den1[(size_t)N_NODES * HEADS];
__device__ float g_as2 [N_NODES];
__device__ float g_ad2 [N_NODES];
__device__ float g_den2[N_NODES];

// ---------------- generic C = A @ B^T, fp32, 64x64 tile ----------------
#define BM 64
#define BN 64
#define BK 16

__global__ void gemm_abT(const float* __restrict__ A, const float* __restrict__ B,
                         float* __restrict__ C, int M, int N, int K) {
    __shared__ float As[BK][BM + 1];
    __shared__ float Bs[BK][BN + 1];
    int bm = blockIdx.y * BM;
    int bn = blockIdx.x * BN;
    int tid = threadIdx.x;           // 256 threads
    int tx = tid & 15, ty = tid >> 4;
    float acc[4][4] = {};
    for (int k0 = 0; k0 < K; k0 += BK) {
        #pragma unroll
        for (int r = 0; r < 4; r++) {
            int j = tid + r * 256;   // 0..1023
            int m = j / BK;          // 0..63
            int k = j % BK;
            int gm = bm + m;
            As[k][m] = (gm < M) ? A[(size_t)gm * K + k0 + k] : 0.f;
            int gn = bn + m;
            Bs[k][m] = (gn < N) ? B[(size_t)gn * K + k0 + k] : 0.f;
        }
        __syncthreads();
        #pragma unroll
        for (int k = 0; k < BK; k++) {
            float a[4], b[4];
            #pragma unroll
            for (int i = 0; i < 4; i++) a[i] = As[k][ty * 4 + i];
            #pragma unroll
            for (int i = 0; i < 4; i++) b[i] = Bs[k][tx * 4 + i];
            #pragma unroll
            for (int i = 0; i < 4; i++)
                #pragma unroll
                for (int j = 0; j < 4; j++)
                    acc[i][j] += a[i] * b[j];
        }
        __syncthreads();
    }
    #pragma unroll
    for (int i = 0; i < 4; i++) {
        int gm = bm + ty * 4 + i;
        if (gm >= M) continue;
        #pragma unroll
        for (int j = 0; j < 4; j++) {
            int gn = bn + tx * 4 + j;
            if (gn < N) C[(size_t)gm * N + gn] = acc[i][j];
        }
    }
}

// ---------------- per-node attention logits, layer 1 (4 heads, warp/head) ----
__global__ void alpha1_kernel(const float* __restrict__ a_src, const float* __restrict__ a_dst) {
    int node = blockIdx.x;
    int h = threadIdx.x >> 5;
    int lane = threadIdx.x & 31;
    const float* row = g_h1 + (size_t)node * H1DIM + h * HID;
    const float* asr = a_src + h * HID;
    const float* adr = a_dst + h * HID;
    float s = 0.f, d = 0.f;
    #pragma unroll
    for (int i = lane; i < HID; i += 32) {
        float v = row[i];
        s += v * asr[i];
        d += v * adr[i];
    }
    #pragma unroll
    for (int o = 16; o; o >>= 1) {
        s += __shfl_down_sync(0xffffffffu, s, o);
        d += __shfl_down_sync(0xffffffffu, d, o);
    }
    if (lane == 0) {
        g_as1[node * HEADS + h] = s;
        g_ad1[node * HEADS + h] = d;
    }
}

__device__ __forceinline__ void edge_sd(int edge, const int* e0, const int* e1, int& src, int& dst) {
    if (edge < E_REAL) { src = e0[edge]; dst = e1[edge]; }
    else { src = dst = edge - E_REAL; }
}

// ---------------- softmax denominators, layer 1 ----------------
__global__ void den1_kernel(const int* __restrict__ e0, const int* __restrict__ e1) {
    int t = blockIdx.x * blockDim.x + threadIdx.x;
    if (t >= E_TOT * HEADS) return;
    int edge = t >> 2, h = t & 3;
    int src, dst; edge_sd(edge, e0, e1, src, dst);
    float ev = g_as1[src * HEADS + h] + g_ad1[dst * HEADS + h];
    ev = ev >= 0.f ? ev : SLOPE * ev;
    atomicAdd(&g_den1[dst * HEADS + h], __expf(ev));
}

// ---------------- weighted scatter, layer 1 (block/edge, 1024 feats) --------
__global__ void scatter1_kernel(const int* __restrict__ e0, const int* __restrict__ e1) {
    int edge = blockIdx.x;
    int src, dst; edge_sd(edge, e0, e1, src, dst);
    int c = threadIdx.x * 4;          // 0..1020
    int h = c >> 8;                   // head for all 4 lanes' elems
    float ev = g_as1[src * HEADS + h] + g_ad1[dst * HEADS + h];
    ev = ev >= 0.f ? ev : SLOPE * ev;
    float w = __expf(ev) / (g_den1[dst * HEADS + h] + 1e-16f);
    float4 v = *(const float4*)(g_h1 + (size_t)src * H1DIM + c);
    float* o = g_agg1 + (size_t)dst * H1DIM + c;
    atomicAdd(o + 0, v.x * w);
    atomicAdd(o + 1, v.y * w);
    atomicAdd(o + 2, v.z * w);
    atomicAdd(o + 3, v.w * w);
}

// ---------------- bias + ELU (in place) ----------------
__global__ void bias_elu_kernel(float* __restrict__ data, const float* __restrict__ b,
                                int n, int cols) {
    int t = blockIdx.x * blockDim.x + threadIdx.x;
    if (t >= n) return;
    float v = data[t] + b[t % cols];
    data[t] = v > 0.f ? v : expm1f(v);
}

// ---------------- per-node attention logits, layer 2 (warp/node) -----------
__global__ void alpha2_kernel(const float* __restrict__ a_src, const float* __restrict__ a_dst) {
    int node = blockIdx.x * (blockDim.x >> 5) + (threadIdx.x >> 5);
    if (node >= N_NODES) return;
    int lane = threadIdx.x & 31;
    float s = 0.f, d = 0.f;
    #pragma unroll
    for (int i = lane; i < EMB; i += 32) {
        float v = g_hh2[(size_t)node * EMB + i];
        s += v * a_src[i];
        d += v * a_dst[i];
    }
    #pragma unroll
    for (int o = 16; o; o >>= 1) {
        s += __shfl_down_sync(0xffffffffu, s, o);
        d += __shfl_down_sync(0xffffffffu, d, o);
    }
    if (lane == 0) { g_as2[node] = s; g_ad2[node] = d; }
}

__global__ void den2_kernel(const int* __restrict__ e0, const int* __restrict__ e1) {
    int edge = blockIdx.x * blockDim.x + threadIdx.x;
    if (edge >= E_TOT) return;
    int src, dst; edge_sd(edge, e0, e1, src, dst);
    float ev = g_as2[src] + g_ad2[dst];
    ev = ev >= 0.f ? ev : SLOPE * ev;
    atomicAdd(&g_den2[dst], __expf(ev));
}

// ---------------- weighted scatter, layer 2 (warp/edge, 128 feats) ---------
__global__ void scatter2_kernel(const int* __restrict__ e0, const int* __restrict__ e1,
                                float* __restrict__ zout) {
    int edge = blockIdx.x * (blockDim.x >> 5) + (threadIdx.x >> 5);
    if (edge >= E_TOT) return;
    int lane = threadIdx.x & 31;
    int src, dst; edge_sd(edge, e0, e1, src, dst);
    float ev = g_as2[src] + g_ad2[dst];
    ev = ev >= 0.f ? ev : SLOPE * ev;
    float w = __expf(ev) / (g_den2[dst] + 1e-16f);
    float4 v = *(const float4*)(g_hh2 + (size_t)src * EMB + lane * 4);
    float* o = zout + (size_t)dst * EMB + lane * 4;
    atomicAdd(o + 0, v.x * w);
    atomicAdd(o + 1, v.y * w);
    atomicAdd(o + 2, v.z * w);
    atomicAdd(o + 3, v.w * w);
}

// ---------------- classifier logits (warp/node) ----------------
__global__ void logits_kernel(const float* __restrict__ z, const float* __restrict__ cls_W,
                              const float* __restrict__ cls_b, float* __restrict__ out) {
    int node = blockIdx.x * (blockDim.x >> 5) + (threadIdx.x >> 5);
    if (node >= N_NODES) return;
    int lane = threadIdx.x & 31;
    float4 zv = *(const float4*)(z + (size_t)node * EMB + lane * 4);
    float acc[4];
    #pragma unroll
    for (int k = 0; k < 4; k++) {
        float4 wv = *(const float4*)(cls_W + k * EMB + lane * 4);
        acc[k] = zv.x * wv.x + zv.y * wv.y + zv.z * wv.z + zv.w * wv.w;
    }
    #pragma unroll
    for (int k = 0; k < 4; k++)
        #pragma unroll
        for (int o = 16; o; o >>= 1) acc[k] += __shfl_down_sync(0xffffffffu, acc[k], o);
    if (lane == 0) {
        #pragma unroll
        for (int k = 0; k < 4; k++)
            out[LOG_OFF + (size_t)node * 4 + k] = acc[k] + cls_b[k];
    }
}

// ---------------- link predictions (warp/pair) ----------------
__global__ void preds_kernel(const float* __restrict__ z, const int* __restrict__ p,
                             const int* __restrict__ nn, float* __restrict__ out) {
    int pair = blockIdx.x * (blockDim.x >> 5) + (threadIdx.x >> 5);
    if (pair >= 2 * P_EDGES) return;
    int lane = threadIdx.x & 31;
    int a, b;
    if (pair < P_EDGES) { a = p[pair]; b = p[P_EDGES + pair]; }
    else { int j = pair - P_EDGES; a = nn[j]; b = nn[P_EDGES + j]; }
    float4 za = *(const float4*)(z + (size_t)a * EMB + lane * 4);
    float4 zb = *(const float4*)(z + (size_t)b * EMB + lane * 4);
    float s = za.x * zb.x + za.y * zb.y + za.z * zb.z + za.w * zb.w;
    #pragma unroll
    for (int o = 16; o; o >>= 1) s += __shfl_down_sync(0xffffffffu, s, o);
    if (lane == 0) out[PRED_OFF + pair] = 1.f / (1.f + __expf(-s));
}

// ============================================================================
extern "C" void kernel_launch(void* const* d_in, const int* in_sizes, int n_in,
                              void* d_out, int out_size) {
    const float* x      = (const float*)d_in[0];
    const int*   e      = (const int*)  d_in[1];
    const int*   p      = (const int*)  d_in[2];
    const int*   nn     = (const int*)  d_in[3];
    const float* W1     = (const float*)d_in[4];
    const float* a_src1 = (const float*)d_in[5];
    const float* a_dst1 = (const float*)d_in[6];
    const float* b1     = (const float*)d_in[7];
    const float* W2     = (const float*)d_in[8];
    const float* a_src2 = (const float*)d_in[9];
    const float* a_dst2 = (const float*)d_in[10];
    const float* b2     = (const float*)d_in[11];
    const float* cls_W  = (const float*)d_in[12];
    const float* cls_b  = (const float*)d_in[13];
    float* out = (float*)d_out;

    const int* e0 = e;
    const int* e1 = e + E_REAL;

    float *agg1, *den1, *den2, *hh2;
    cudaGetSymbolAddress((void**)&agg1, g_agg1);
    cudaGetSymbolAddress((void**)&den1, g_den1);
    cudaGetSymbolAddress((void**)&den2, g_den2);
    cudaGetSymbolAddress((void**)&hh2,  g_hh2);

    // zero accumulators (+ z region of out)
    cudaMemsetAsync(agg1, 0, (size_t)N_NODES * H1DIM * sizeof(float));
    cudaMemsetAsync(den1, 0, (size_t)N_NODES * HEADS * sizeof(float));
    cudaMemsetAsync(den2, 0, (size_t)N_NODES * sizeof(float));
    cudaMemsetAsync(out,  0, Z_ELEMS * sizeof(float));

    float* h1;
    cudaGetSymbolAddress((void**)&h1, g_h1);

    // ---- layer 1 ----
    {
        dim3 grid(H1DIM / BN, (N_NODES + BM - 1) / BM);
        gemm_abT<<<grid, 256>>>(x, W1, h1, N_NODES, H1DIM, DIM);
    }
    alpha1_kernel<<<N_NODES, 128>>>(a_src1, a_dst1);
    den1_kernel<<<(E_TOT * HEADS + 255) / 256, 256>>>(e0, e1);
    scatter1_kernel<<<E_TOT, 256>>>(e0, e1);
    bias_elu_kernel<<<((int)((size_t)N_NODES * H1DIM) + 255) / 256, 256>>>(
        agg1, b1, N_NODES * H1DIM, H1DIM);

    // ---- layer 2 ----
    {
        dim3 grid(EMB / BN, (N_NODES + BM - 1) / BM);
        gemm_abT<<<grid, 256>>>(agg1, W2, hh2, N_NODES, EMB, H1DIM);
    }
    alpha2_kernel<<<(N_NODES * 32 + 255) / 256, 256>>>(a_src2, a_dst2);
    den2_kernel<<<(E_TOT + 255) / 256, 256>>>(e0, e1);
    scatter2_kernel<<<(E_TOT + 7) / 8, 256>>>(e0, e1, out);
    bias_elu_kernel<<<((int)Z_ELEMS + 255) / 256, 256>>>(out, b2, (int)Z_ELEMS, EMB);

    // ---- heads ----
    logits_kernel<<<(N_NODES + 7) / 8, 256>>>(out, cls_W, cls_b, out);
    preds_kernel<<<(2 * P_EDGES + 7) / 8, 256>>>(out, p, nn, out);
}

// round 4
// speedup vs baseline: 1.9085x; 1.9085x over previous
#include <cuda_runtime.h>
#include <cuda_bf16.h>
#include <cstdint>

#define N_NODES 50000
#define DIM     128
#define E_REAL  200000
#define E_TOT   250000   // + self loops
#define P_EDGES 50000
#define HEADS   4
#define HID     256
#define H1DIM   1024     // HEADS*HID
#define EMB     128
#define SLOPE   0.2f

#define Z_ELEMS   ((size_t)N_NODES * EMB)          // 6.4M
#define LOG_OFF   (Z_ELEMS)                        // logits at 6.4M
#define PRED_OFF  (Z_ELEMS + (size_t)N_NODES * 4)  // preds at 6.6M

// ---------------- scratch (device globals; no allocs allowed) ----------------
__device__ float g_h1  [(size_t)N_NODES * H1DIM];  // layer1 features (pre-agg)
__device__ float g_agg1[(size_t)N_NODES * H1DIM];  // layer1 aggregated (post elu) = layer2 input
__device__ float g_hh2 [(size_t)N_NODES * EMB];    // layer2 features (pre-agg)
__device__ float g_as1 [(size_t)N_NODES * HEADS];
__device__ float g_ad1 [(size_t)N_NODES * HEADS];
__device__ float g_as2 [N_NODES];
__device__ float g_ad2 [N_NODES];

// CSR by destination
__device__ int g_deg[N_NODES];
__device__ int g_off[N_NODES + 1];
__device__ int g_cur[N_NODES];
__device__ int g_eid[E_TOT];

// ======================= GEMM: C = A @ B^T (fp32) ===========================
// 128x128 block tile, 8x8 per thread, 256 threads.
#define GBM 128
#define GBN 128
#define GBK 16

__global__ __launch_bounds__(256, 2)
void gemm_abT(const float* __restrict__ A, const float* __restrict__ B,
              float* __restrict__ C, int M, int N, int K) {
    __shared__ float As[GBK][GBM];
    __shared__ float Bs[GBK][GBN];
    int bm = blockIdx.y * GBM;
    int bn = blockIdx.x * GBN;
    int tid = threadIdx.x;            // 0..255
    int tx = tid & 15, ty = tid >> 4; // 16 x 16 thread grid
    float acc[8][8] = {};

    for (int k0 = 0; k0 < K; k0 += GBK) {
        // Load A tile: 128 rows x 16 k = 512 float4, 2 per thread. Same for B.
        #pragma unroll
        for (int l = 0; l < 2; l++) {
            int i = tid * 2 + l;       // 0..511
            int r = i >> 2, kq = i & 3;
            int gm = bm + r;
            float4 va = (gm < M) ? *(const float4*)(A + (size_t)gm * K + k0 + kq * 4)
                                 : make_float4(0.f, 0.f, 0.f, 0.f);
            As[kq * 4 + 0][r] = va.x; As[kq * 4 + 1][r] = va.y;
            As[kq * 4 + 2][r] = va.z; As[kq * 4 + 3][r] = va.w;
            int gn = bn + r;
            float4 vb = (gn < N) ? *(const float4*)(B + (size_t)gn * K + k0 + kq * 4)
                                 : make_float4(0.f, 0.f, 0.f, 0.f);
            Bs[kq * 4 + 0][r] = vb.x; Bs[kq * 4 + 1][r] = vb.y;
            Bs[kq * 4 + 2][r] = vb.z; Bs[kq * 4 + 3][r] = vb.w;
        }
        __syncthreads();
        #pragma unroll
        for (int k = 0; k < GBK; k++) {
            float a[8], b[8];
            *(float4*)&a[0] = *(const float4*)&As[k][ty * 8];
            *(float4*)&a[4] = *(const float4*)&As[k][ty * 8 + 4];
            *(float4*)&b[0] = *(const float4*)&Bs[k][tx * 8];
            *(float4*)&b[4] = *(const float4*)&Bs[k][tx * 8 + 4];
            #pragma unroll
            for (int i = 0; i < 8; i++)
                #pragma unroll
                for (int j = 0; j < 8; j++)
                    acc[i][j] += a[i] * b[j];
        }
        __syncthreads();
    }
    // Epilogue. N is always a multiple of 128 here; only M needs bounds.
    #pragma unroll
    for (int i = 0; i < 8; i++) {
        int gm = bm + ty * 8 + i;
        if (gm >= M) continue;
        float* row = C + (size_t)gm * N + bn + tx * 8;
        *(float4*)(row)     = *(float4*)&acc[i][0];
        *(float4*)(row + 4) = *(float4*)&acc[i][4];
    }
}

// ======================= CSR build (by destination) =========================
__global__ void csr_count(const int* __restrict__ e1) {
    int t = blockIdx.x * blockDim.x + threadIdx.x;
    if (t >= E_TOT) return;
    int dst = (t < E_REAL) ? e1[t] : t - E_REAL;
    atomicAdd(&g_deg[dst], 1);
}

// single block, 1024 threads: exclusive scan of g_deg -> g_off (+ g_cur copy)
__global__ void csr_scan() {
    __shared__ int s[1024];
    const int per = (N_NODES + 1023) / 1024;  // 49
    int tid = threadIdx.x;
    int base = tid * per;
    int sum = 0;
    for (int i = 0; i < per; i++) {
        int idx = base + i;
        if (idx < N_NODES) sum += g_deg[idx];
    }
    s[tid] = sum;
    __syncthreads();
    for (int off = 1; off < 1024; off <<= 1) {
        int v = (tid >= off) ? s[tid - off] : 0;
        __syncthreads();
        s[tid] += v;
        __syncthreads();
    }
    int run = (tid > 0) ? s[tid - 1] : 0;   // exclusive
    for (int i = 0; i < per; i++) {
        int idx = base + i;
        if (idx < N_NODES) {
            g_off[idx] = run;
            g_cur[idx] = run;
            run += g_deg[idx];
        }
    }
    if (tid == 0) g_off[N_NODES] = E_TOT;
}

__global__ void csr_place(const int* __restrict__ e1) {
    int t = blockIdx.x * blockDim.x + threadIdx.x;
    if (t >= E_TOT) return;
    int dst = (t < E_REAL) ? e1[t] : t - E_REAL;
    int pos = atomicAdd(&g_cur[dst], 1);
    g_eid[pos] = t;
}

// ================== per-node attention logits, layer 1 ======================
__global__ void alpha1_kernel(const float* __restrict__ a_src, const float* __restrict__ a_dst) {
    int node = blockIdx.x;
    int h = threadIdx.x >> 5;
    int lane = threadIdx.x & 31;
    const float* row = g_h1 + (size_t)node * H1DIM + h * HID;
    const float* asr = a_src + h * HID;
    const float* adr = a_dst + h * HID;
    float s = 0.f, d = 0.f;
    #pragma unroll
    for (int i = lane; i < HID; i += 32) {
        float v = row[i];
        s += v * asr[i];
        d += v * adr[i];
    }
    #pragma unroll
    for (int o = 16; o; o >>= 1) {
        s += __shfl_down_sync(0xffffffffu, s, o);
        d += __shfl_down_sync(0xffffffffu, d, o);
    }
    if (lane == 0) {
        g_as1[node * HEADS + h] = s;
        g_ad1[node * HEADS + h] = d;
    }
}

// ========== layer-1 gather: softmax + weighted agg + bias + ELU =============
// one block (256 threads) per destination node; thread owns 4 consecutive feats
__global__ void gather1_kernel(const int* __restrict__ e0, const float* __restrict__ b1) {
    int node = blockIdx.x;
    int beg = g_off[node], end = g_off[node + 1];
    int c = threadIdx.x * 4;          // 0..1020
    int h = c >> 8;                   // same head for all 4 feats
    float adh = g_ad1[node * HEADS + h];

    // pass 1: denominator for this head (redundant across the 64 threads/head)
    float den = 0.f;
    for (int e = beg; e < end; e++) {
        int id = g_eid[e];
        int src = (id < E_REAL) ? e0[id] : id - E_REAL;
        float ev = g_as1[src * HEADS + h] + adh;
        ev = ev >= 0.f ? ev : SLOPE * ev;
        den += __expf(ev);
    }
    float inv_den = 1.f / (den + 1e-16f);

    // pass 2: weighted accumulation
    float4 acc = make_float4(0.f, 0.f, 0.f, 0.f);
    for (int e = beg; e < end; e++) {
        int id = g_eid[e];
        int src = (id < E_REAL) ? e0[id] : id - E_REAL;
        float ev = g_as1[src * HEADS + h] + adh;
        ev = ev >= 0.f ? ev : SLOPE * ev;
        float w = __expf(ev) * inv_den;
        float4 v = *(const float4*)(g_h1 + (size_t)src * H1DIM + c);
        acc.x += v.x * w; acc.y += v.y * w; acc.z += v.z * w; acc.w += v.w * w;
    }
    // bias + ELU
    float4 bv = *(const float4*)(b1 + c);
    acc.x += bv.x; acc.y += bv.y; acc.z += bv.z; acc.w += bv.w;
    acc.x = acc.x > 0.f ? acc.x : expm1f(acc.x);
    acc.y = acc.y > 0.f ? acc.y : expm1f(acc.y);
    acc.z = acc.z > 0.f ? acc.z : expm1f(acc.z);
    acc.w = acc.w > 0.f ? acc.w : expm1f(acc.w);
    *(float4*)(g_agg1 + (size_t)node * H1DIM + c) = acc;
}

// ================== per-node attention logits, layer 2 ======================
__global__ void alpha2_kernel(const float* __restrict__ a_src, const float* __restrict__ a_dst) {
    int node = blockIdx.x * (blockDim.x >> 5) + (threadIdx.x >> 5);
    if (node >= N_NODES) return;
    int lane = threadIdx.x & 31;
    float s = 0.f, d = 0.f;
    #pragma unroll
    for (int i = lane; i < EMB; i += 32) {
        float v = g_hh2[(size_t)node * EMB + i];
        s += v * a_src[i];
        d += v * a_dst[i];
    }
    #pragma unroll
    for (int o = 16; o; o >>= 1) {
        s += __shfl_down_sync(0xffffffffu, s, o);
        d += __shfl_down_sync(0xffffffffu, d, o);
    }
    if (lane == 0) { g_as2[node] = s; g_ad2[node] = d; }
}

// ========== layer-2 gather: softmax + weighted agg + bias + ELU -> z ========
// one block (128 threads) per destination node; thread owns 1 feature
__global__ void gather2_kernel(const int* __restrict__ e0, const float* __restrict__ b2,
                               float* __restrict__ zout) {
    int node = blockIdx.x;
    int beg = g_off[node], end = g_off[node + 1];
    int c = threadIdx.x;
    float adn = g_ad2[node];

    float den = 0.f;
    for (int e = beg; e < end; e++) {
        int id = g_eid[e];
        int src = (id < E_REAL) ? e0[id] : id - E_REAL;
        float ev = g_as2[src] + adn;
        ev = ev >= 0.f ? ev : SLOPE * ev;
        den += __expf(ev);
    }
    float inv_den = 1.f / (den + 1e-16f);

    float acc = 0.f;
    for (int e = beg; e < end; e++) {
        int id = g_eid[e];
        int src = (id < E_REAL) ? e0[id] : id - E_REAL;
        float ev = g_as2[src] + adn;
        ev = ev >= 0.f ? ev : SLOPE * ev;
        float w = __expf(ev) * inv_den;
        acc += g_hh2[(size_t)src * EMB + c] * w;
    }
    acc += b2[c];
    acc = acc > 0.f ? acc : expm1f(acc);
    zout[(size_t)node * EMB + c] = acc;
}

// ---------------- classifier logits (warp/node) ----------------
__global__ void logits_kernel(const float* __restrict__ z, const float* __restrict__ cls_W,
                              const float* __restrict__ cls_b, float* __restrict__ out) {
    int node = blockIdx.x * (blockDim.x >> 5) + (threadIdx.x >> 5);
    if (node >= N_NODES) return;
    int lane = threadIdx.x & 31;
    float4 zv = *(const float4*)(z + (size_t)node * EMB + lane * 4);
    float acc[4];
    #pragma unroll
    for (int k = 0; k < 4; k++) {
        float4 wv = *(const float4*)(cls_W + k * EMB + lane * 4);
        acc[k] = zv.x * wv.x + zv.y * wv.y + zv.z * wv.z + zv.w * wv.w;
    }
    #pragma unroll
    for (int k = 0; k < 4; k++)
        #pragma unroll
        for (int o = 16; o; o >>= 1) acc[k] += __shfl_down_sync(0xffffffffu, acc[k], o);
    if (lane == 0) {
        #pragma unroll
        for (int k = 0; k < 4; k++)
            out[LOG_OFF + (size_t)node * 4 + k] = acc[k] + cls_b[k];
    }
}

// ---------------- link predictions (warp/pair) ----------------
__global__ void preds_kernel(const float* __restrict__ z, const int* __restrict__ p,
                             const int* __restrict__ nn, float* __restrict__ out) {
    int pair = blockIdx.x * (blockDim.x >> 5) + (threadIdx.x >> 5);
    if (pair >= 2 * P_EDGES) return;
    int lane = threadIdx.x & 31;
    int a, b;
    if (pair < P_EDGES) { a = p[pair]; b = p[P_EDGES + pair]; }
    else { int j = pair - P_EDGES; a = nn[j]; b = nn[P_EDGES + j]; }
    float4 za = *(const float4*)(z + (size_t)a * EMB + lane * 4);
    float4 zb = *(const float4*)(z + (size_t)b * EMB + lane * 4);
    float s = za.x * zb.x + za.y * zb.y + za.z * zb.z + za.w * zb.w;
    #pragma unroll
    for (int o = 16; o; o >>= 1) s += __shfl_down_sync(0xffffffffu, s, o);
    if (lane == 0) out[PRED_OFF + pair] = 1.f / (1.f + __expf(-s));
}

// ============================================================================
extern "C" void kernel_launch(void* const* d_in, const int* in_sizes, int n_in,
                              void* d_out, int out_size) {
    const float* x      = (const float*)d_in[0];
    const int*   e      = (const int*)  d_in[1];
    const int*   p      = (const int*)  d_in[2];
    const int*   nn     = (const int*)  d_in[3];
    const float* W1     = (const float*)d_in[4];
    const float* a_src1 = (const float*)d_in[5];
    const float* a_dst1 = (const float*)d_in[6];
    const float* b1     = (const float*)d_in[7];
    const float* W2     = (const float*)d_in[8];
    const float* a_src2 = (const float*)d_in[9];
    const float* a_dst2 = (const float*)d_in[10];
    const float* b2     = (const float*)d_in[11];
    const float* cls_W  = (const float*)d_in[12];
    const float* cls_b  = (const float*)d_in[13];
    float* out = (float*)d_out;

    const int* e0 = e;
    const int* e1 = e + E_REAL;

    float *h1, *agg1, *hh2;
    int* deg;
    cudaGetSymbolAddress((void**)&h1,   g_h1);
    cudaGetSymbolAddress((void**)&agg1, g_agg1);
    cudaGetSymbolAddress((void**)&hh2,  g_hh2);
    cudaGetSymbolAddress((void**)&deg,  g_deg);

    // ---- CSR build (by destination) ----
    cudaMemsetAsync(deg, 0, N_NODES * sizeof(int));
    csr_count<<<(E_TOT + 255) / 256, 256>>>(e1);
    csr_scan<<<1, 1024>>>();
    csr_place<<<(E_TOT + 255) / 256, 256>>>(e1);

    // ---- layer 1 ----
    {
        dim3 grid(H1DIM / GBN, (N_NODES + GBM - 1) / GBM);
        gemm_abT<<<grid, 256>>>(x, W1, h1, N_NODES, H1DIM, DIM);
    }
    alpha1_kernel<<<N_NODES, 128>>>(a_src1, a_dst1);
    gather1_kernel<<<N_NODES, 256>>>(e0, b1);   // fused den + agg + bias + ELU

    // ---- layer 2 ----
    {
        dim3 grid(EMB / GBN, (N_NODES + GBM - 1) / GBM);
        gemm_abT<<<grid, 256>>>(agg1, W2, hh2, N_NODES, EMB, H1DIM);
    }
    alpha2_kernel<<<(N_NODES * 32 + 255) / 256, 256>>>(a_src2, a_dst2);
    gather2_kernel<<<N_NODES, 128>>>(e0, b2, out);  // writes z directly

    // ---- heads ----
    logits_kernel<<<(N_NODES + 7) / 8, 256>>>(out, cls_W, cls_b, out);
    preds_kernel<<<(2 * P_EDGES + 7) / 8, 256>>>(out, p, nn, out);
}

// round 6
// speedup vs baseline: 2.0741x; 1.0868x over previous
#include <cuda_runtime.h>
#include <cuda_bf16.h>
#include <cstdint>

#define N_NODES 50000
#define DIM     128
#define E_REAL  200000
#define E_TOT   250000   // + self loops
#define P_EDGES 50000
#define HEADS   4
#define HID     256
#define H1DIM   1024     // HEADS*HID
#define EMB     128
#define SLOPE   0.2f

#define Z_ELEMS   ((size_t)N_NODES * EMB)          // 6.4M
#define LOG_OFF   (Z_ELEMS)                        // logits at 6.4M
#define PRED_OFF  (Z_ELEMS + (size_t)N_NODES * 4)  // preds at 6.6M

// ---------------- scratch (device globals; no allocs allowed) ----------------
__device__ float g_aggx[(size_t)N_NODES * HEADS * DIM]; // per-head aggregated x [N,4,128]
__device__ float g_h1  [(size_t)N_NODES * H1DIM];       // layer1 output (post bias+ELU)
__device__ float g_hh2 [(size_t)N_NODES * EMB];         // layer2 features (pre-agg)
__device__ float g_as1 [(size_t)N_NODES * HEADS];
__device__ float g_ad1 [(size_t)N_NODES * HEADS];
__device__ float g_as2 [N_NODES];
__device__ float g_ad2 [N_NODES];
__device__ float g_v1s [HEADS * DIM];   // W1^T a_src1 per head
__device__ float g_v1d [HEADS * DIM];   // W1^T a_dst1 per head

// CSR by destination
__device__ int g_deg[N_NODES];
__device__ int g_off[N_NODES + 1];
__device__ int g_cur[N_NODES];
__device__ int g_eid[E_TOT];

// ======================= GEMM: C = A @ B^T (fp32) ===========================
// 128x128 block tile, 8x8 per thread, 256 threads.
// head_span>0: A column window = (blockIdx.x/head_span)*headK (grouped GEMM).
// bias!=null: fused bias (+ ELU if do_elu).
#define GBM 128
#define GBN 128
#define GBK 16

__global__ __launch_bounds__(256, 2)
void gemm_abT(const float* __restrict__ A, const float* __restrict__ B,
              float* __restrict__ C, int M, int N, int K, int lda,
              int head_span, int headK,
              const float* __restrict__ bias, int do_elu) {
    __shared__ float As[GBK][GBM];
    __shared__ float Bs[GBK][GBN];
    int bm = blockIdx.y * GBM;
    int bn = blockIdx.x * GBN;
    int a_off = head_span ? (blockIdx.x / head_span) * headK : 0;
    int tid = threadIdx.x;            // 0..255
    int tx = tid & 15, ty = tid >> 4; // 16 x 16 thread grid
    float acc[8][8] = {};

    for (int k0 = 0; k0 < K; k0 += GBK) {
        #pragma unroll
        for (int l = 0; l < 2; l++) {
            int i = tid * 2 + l;       // 0..511
            int r = i >> 2, kq = i & 3;
            int gm = bm + r;
            float4 va = (gm < M) ? *(const float4*)(A + (size_t)gm * lda + a_off + k0 + kq * 4)
                                 : make_float4(0.f, 0.f, 0.f, 0.f);
            As[kq * 4 + 0][r] = va.x; As[kq * 4 + 1][r] = va.y;
            As[kq * 4 + 2][r] = va.z; As[kq * 4 + 3][r] = va.w;
            int gn = bn + r;
            float4 vb = (gn < N) ? *(const float4*)(B + (size_t)gn * K + k0 + kq * 4)
                                 : make_float4(0.f, 0.f, 0.f, 0.f);
            Bs[kq * 4 + 0][r] = vb.x; Bs[kq * 4 + 1][r] = vb.y;
            Bs[kq * 4 + 2][r] = vb.z; Bs[kq * 4 + 3][r] = vb.w;
        }
        __syncthreads();
        #pragma unroll
        for (int k = 0; k < GBK; k++) {
            float a[8], b[8];
            *(float4*)&a[0] = *(const float4*)&As[k][ty * 8];
            *(float4*)&a[4] = *(const float4*)&As[k][ty * 8 + 4];
            *(float4*)&b[0] = *(const float4*)&Bs[k][tx * 8];
            *(float4*)&b[4] = *(const float4*)&Bs[k][tx * 8 + 4];
            #pragma unroll
            for (int i = 0; i < 8; i++)
                #pragma unroll
                for (int j = 0; j < 8; j++)
                    acc[i][j] += a[i] * b[j];
        }
        __syncthreads();
    }
    float bv[8];
    if (bias) {
        #pragma unroll
        for (int j = 0; j < 8; j++) bv[j] = bias[bn + tx * 8 + j];
    }
    #pragma unroll
    for (int i = 0; i < 8; i++) {
        int gm = bm + ty * 8 + i;
        if (gm >= M) continue;
        float* row = C + (size_t)gm * N + bn + tx * 8;
        if (bias) {
            #pragma unroll
            for (int j = 0; j < 8; j++) {
                float v = acc[i][j] + bv[j];
                if (do_elu) v = v > 0.f ? v : expm1f(v);
                acc[i][j] = v;
            }
        }
        *(float4*)(row)     = *(float4*)&acc[i][0];
        *(float4*)(row + 4) = *(float4*)&acc[i][4];
    }
}

// ======================= CSR build (by destination) =========================
__global__ void csr_count(const int* __restrict__ e1) {
    int t = blockIdx.x * blockDim.x + threadIdx.x;
    if (t >= E_TOT) return;
    int dst = (t < E_REAL) ? e1[t] : t - E_REAL;
    atomicAdd(&g_deg[dst], 1);
}

__global__ void csr_scan() {
    __shared__ int s[1024];
    const int per = (N_NODES + 1023) / 1024;  // 49
    int tid = threadIdx.x;
    int base = tid * per;
    int sum = 0;
    for (int i = 0; i < per; i++) {
        int idx = base + i;
        if (idx < N_NODES) sum += g_deg[idx];
    }
    s[tid] = sum;
    __syncthreads();
    for (int off = 1; off < 1024; off <<= 1) {
        int v = (tid >= off) ? s[tid - off] : 0;
        __syncthreads();
        s[tid] += v;
        __syncthreads();
    }
    int run = (tid > 0) ? s[tid - 1] : 0;   // exclusive
    for (int i = 0; i < per; i++) {
        int idx = base + i;
        if (idx < N_NODES) {
            g_off[idx] = run;
            g_cur[idx] = run;
            run += g_deg[idx];
        }
    }
    if (tid == 0) g_off[N_NODES] = E_TOT;
}

__global__ void csr_place(const int* __restrict__ e1) {
    int t = blockIdx.x * blockDim.x + threadIdx.x;
    if (t >= E_TOT) return;
    int dst = (t < E_REAL) ? e1[t] : t - E_REAL;
    int pos = atomicAdd(&g_cur[dst], 1);
    g_eid[pos] = t;
}

// ============== v = W1^T a (rank-4 projections for layer-1 alphas) ==========
__global__ void proj_v(const float* __restrict__ W1, const float* __restrict__ as,
                       const float* __restrict__ ad) {
    int o = blockIdx.x * blockDim.x + threadIdx.x;  // 0..1023
    if (o >= 2 * HEADS * DIM) return;
    int set = o >> 9;          // 0=src, 1=dst
    int h = (o >> 7) & 3;
    int c = o & 127;
    const float* a = set ? ad : as;
    float s = 0.f;
    for (int j = 0; j < HID; j++)
        s += a[h * HID + j] * W1[(size_t)(h * HID + j) * DIM + c];
    (set ? g_v1d : g_v1s)[h * DIM + c] = s;
}

// ============== layer-1 alphas directly from x (warp per node) ==============
__global__ void alpha1x_kernel(const float* __restrict__ x) {
    int node = blockIdx.x * (blockDim.x >> 5) + (threadIdx.x >> 5);
    if (node >= N_NODES) return;
    int lane = threadIdx.x & 31;
    float4 xv = ((const float4*)x)[(size_t)node * 32 + lane];
    float s[HEADS], d[HEADS];
    #pragma unroll
    for (int h = 0; h < HEADS; h++) {
        float4 vs = ((const float4*)g_v1s)[h * 32 + lane];
        float4 vd = ((const float4*)g_v1d)[h * 32 + lane];
        s[h] = xv.x * vs.x + xv.y * vs.y + xv.z * vs.z + xv.w * vs.w;
        d[h] = xv.x * vd.x + xv.y * vd.y + xv.z * vd.z + xv.w * vd.w;
    }
    #pragma unroll
    for (int o = 16; o; o >>= 1) {
        #pragma unroll
        for (int h = 0; h < HEADS; h++) {
            s[h] += __shfl_xor_sync(0xffffffffu, s[h], o);
            d[h] += __shfl_xor_sync(0xffffffffu, d[h], o);
        }
    }
    if (lane == 0) {
        #pragma unroll
        for (int h = 0; h < HEADS; h++) {
            g_as1[node * HEADS + h] = s[h];
            g_ad1[node * HEADS + h] = d[h];
        }
    }
}

// ====== layer-1 gather on x: softmax + per-head weighted agg of x[src] ======
// warp per destination node; lane owns one float4 of the 128-dim x row.
__global__ void gatherx_kernel(const float* __restrict__ x, const int* __restrict__ e0) {
    int node = blockIdx.x * (blockDim.x >> 5) + (threadIdx.x >> 5);
    if (node >= N_NODES) return;
    int lane = threadIdx.x & 31;
    int beg = g_off[node], end = g_off[node + 1];

    float adh = (lane < HEADS) ? g_ad1[node * HEADS + lane] : 0.f;
    float den = 0.f;
    for (int e = beg; e < end; e++) {
        int id = g_eid[e];
        int src = (id < E_REAL) ? e0[id] : node;
        if (lane < HEADS) {
            float ev = g_as1[src * HEADS + lane] + adh;
            ev = ev >= 0.f ? ev : SLOPE * ev;
            den += __expf(ev);
        }
    }
    float inv = 1.f / (den + 1e-16f);

    float4 a0 = make_float4(0.f,0.f,0.f,0.f), a1 = a0, a2 = a0, a3 = a0;
    for (int e = beg; e < end; e++) {
        int id = g_eid[e];
        int src = (id < E_REAL) ? e0[id] : node;
        float w = 0.f;
        if (lane < HEADS) {
            float ev = g_as1[src * HEADS + lane] + adh;
            ev = ev >= 0.f ? ev : SLOPE * ev;
            w = __expf(ev) * inv;
        }
        float w0 = __shfl_sync(0xffffffffu, w, 0);
        float w1 = __shfl_sync(0xffffffffu, w, 1);
        float w2 = __shfl_sync(0xffffffffu, w, 2);
        float w3 = __shfl_sync(0xffffffffu, w, 3);
        float4 v = ((const float4*)x)[(size_t)src * 32 + lane];
        a0.x += w0*v.x; a0.y += w0*v.y; a0.z += w0*v.z; a0.w += w0*v.w;
        a1.x += w1*v.x; a1.y += w1*v.y; a1.z += w1*v.z; a1.w += w1*v.w;
        a2.x += w2*v.x; a2.y += w2*v.y; a2.z += w2*v.z; a2.w += w2*v.w;
        a3.x += w3*v.x; a3.y += w3*v.y; a3.z += w3*v.z; a3.w += w3*v.w;
    }
    float4* dst = (float4*)(g_aggx + (size_t)node * HEADS * DIM);
    dst[0 * 32 + lane] = a0;
    dst[1 * 32 + lane] = a1;
    dst[2 * 32 + lane] = a2;
    dst[3 * 32 + lane] = a3;
}

// ================== per-node attention logits, layer 2 ======================
__global__ void alpha2_kernel(const float* __restrict__ a_src, const float* __restrict__ a_dst) {
    int node = blockIdx.x * (blockDim.x >> 5) + (threadIdx.x >> 5);
    if (node >= N_NODES) return;
    int lane = threadIdx.x & 31;
    float4 v  = ((const float4*)g_hh2)[(size_t)node * 32 + lane];
    float4 vs = ((const float4*)a_src)[lane];
    float4 vd = ((const float4*)a_dst)[lane];
    float s = v.x*vs.x + v.y*vs.y + v.z*vs.z + v.w*vs.w;
    float d = v.x*vd.x + v.y*vd.y + v.z*vd.z + v.w*vd.w;
    #pragma unroll
    for (int o = 16; o; o >>= 1) {
        s += __shfl_xor_sync(0xffffffffu, s, o);
        d += __shfl_xor_sync(0xffffffffu, d, o);
    }
    if (lane == 0) { g_as2[node] = s; g_ad2[node] = d; }
}

// ====== layer-2 gather: softmax + weighted agg + bias + ELU -> z ============
// warp per destination node; lane owns one float4 of the 128-dim row.
__global__ void gather2_kernel(const int* __restrict__ e0, const float* __restrict__ b2,
                               float* __restrict__ zout) {
    int node = blockIdx.x * (blockDim.x >> 5) + (threadIdx.x >> 5);
    if (node >= N_NODES) return;
    int lane = threadIdx.x & 31;
    int beg = g_off[node], end = g_off[node + 1];
    float adn = g_ad2[node];

    float den = 0.f;
    for (int e = beg; e < end; e++) {
        int id = g_eid[e];
        int src = (id < E_REAL) ? e0[id] : node;
        if (lane == 0) {
            float ev = g_as2[src] + adn;
            ev = ev >= 0.f ? ev : SLOPE * ev;
            den += __expf(ev);
        }
    }
    float inv = 1.f / (den + 1e-16f);

    float4 acc = make_float4(0.f,0.f,0.f,0.f);
    for (int e = beg; e < end; e++) {
        int id = g_eid[e];
        int src = (id < E_REAL) ? e0[id] : node;
        float w = 0.f;
        if (lane == 0) {
            float ev = g_as2[src] + adn;
            ev = ev >= 0.f ? ev : SLOPE * ev;
            w = __expf(ev) * inv;
        }
        w = __shfl_sync(0xffffffffu, w, 0);
        float4 v = ((const float4*)g_hh2)[(size_t)src * 32 + lane];
        acc.x += w*v.x; acc.y += w*v.y; acc.z += w*v.z; acc.w += w*v.w;
    }
    float4 bv = ((const float4*)b2)[lane];
    acc.x += bv.x; acc.y += bv.y; acc.z += bv.z; acc.w += bv.w;
    acc.x = acc.x > 0.f ? acc.x : expm1f(acc.x);
    acc.y = acc.y > 0.f ? acc.y : expm1f(acc.y);
    acc.z = acc.z > 0.f ? acc.z : expm1f(acc.z);
    acc.w = acc.w > 0.f ? acc.w : expm1f(acc.w);
    ((float4*)zout)[(size_t)node * 32 + lane] = acc;
}

// ---------------- classifier logits (warp/node) ----------------
__global__ void logits_kernel(const float* __restrict__ z, const float* __restrict__ cls_W,
                              const float* __restrict__ cls_b, float* __restrict__ out) {
    int node = blockIdx.x * (blockDim.x >> 5) + (threadIdx.x >> 5);
    if (node >= N_NODES) return;
    int lane = threadIdx.x & 31;
    float4 zv = *(const float4*)(z + (size_t)node * EMB + lane * 4);
    float acc[4];
    #pragma unroll
    for (int k = 0; k < 4; k++) {
        float4 wv = *(const float4*)(cls_W + k * EMB + lane * 4);
        acc[k] = zv.x * wv.x + zv.y * wv.y + zv.z * wv.z + zv.w * wv.w;
    }
    #pragma unroll
    for (int k = 0; k < 4; k++)
        #pragma unroll
        for (int o = 16; o; o >>= 1) acc[k] += __shfl_down_sync(0xffffffffu, acc[k], o);
    if (lane == 0) {
        #pragma unroll
        for (int k = 0; k < 4; k++)
            out[LOG_OFF + (size_t)node * 4 + k] = acc[k] + cls_b[k];
    }
}

// ---------------- link predictions (warp/pair) ----------------
__global__ void preds_kernel(const float* __restrict__ z, const int* __restrict__ p,
                             const int* __restrict__ nn, float* __restrict__ out) {
    int pair = blockIdx.x * (blockDim.x >> 5) + (threadIdx.x >> 5);
    if (pair >= 2 * P_EDGES) return;
    int lane = threadIdx.x & 31;
    int a, b;
    if (pair < P_EDGES) { a = p[pair]; b = p[P_EDGES + pair]; }
    else { int j = pair - P_EDGES; a = nn[j]; b = nn[P_EDGES + j]; }
    float4 za = *(const float4*)(z + (size_t)a * EMB + lane * 4);
    float4 zb = *(const float4*)(z + (size_t)b * EMB + lane * 4);
    float s = za.x * zb.x + za.y * zb.y + za.z * zb.z + za.w * zb.w;
    #pragma unroll
    for (int o = 16; o; o >>= 1) s += __shfl_down_sync(0xffffffffu, s, o);
    if (lane == 0) out[PRED_OFF + pair] = 1.f / (1.f + __expf(-s));
}

// ============================================================================
extern "C" void kernel_launch(void* const* d_in, const int* in_sizes, int n_in,
                              void* d_out, int out_size) {
    const float* x      = (const float*)d_in[0];
    const int*   e      = (const int*)  d_in[1];
    const int*   p      = (const int*)  d_in[2];
    const int*   nn     = (const int*)  d_in[3];
    const float* W1     = (const float*)d_in[4];
    const float* a_src1 = (const float*)d_in[5];
    const float* a_dst1 = (const float*)d_in[6];
    const float* b1     = (const float*)d_in[7];
    const float* W2     = (const float*)d_in[8];
    const float* a_src2 = (const float*)d_in[9];
    const float* a_dst2 = (const float*)d_in[10];
    const float* b2     = (const float*)d_in[11];
    const float* cls_W  = (const float*)d_in[12];
    const float* cls_b  = (const float*)d_in[13];
    float* out = (float*)d_out;

    const int* e0 = e;
    const int* e1 = e + E_REAL;

    float *aggx, *h1, *hh2;
    int* deg;
    cudaGetSymbolAddress((void**)&aggx, g_aggx);
    cudaGetSymbolAddress((void**)&h1,   g_h1);
    cudaGetSymbolAddress((void**)&hh2,  g_hh2);
    cudaGetSymbolAddress((void**)&deg,  g_deg);

    // ---- CSR build (by destination) + alpha projections ----
    cudaMemsetAsync(deg, 0, N_NODES * sizeof(int));
    csr_count<<<(E_TOT + 255) / 256, 256>>>(e1);
    csr_scan<<<1, 1024>>>();
    csr_place<<<(E_TOT + 255) / 256, 256>>>(e1);

    proj_v<<<4, 256>>>(W1, a_src1, a_dst1);
    alpha1x_kernel<<<(N_NODES + 7) / 8, 256>>>(x);

    // ---- layer 1: aggregate x per head, then grouped GEMM + bias + ELU ----
    gatherx_kernel<<<(N_NODES + 7) / 8, 256>>>(x, e0);
    {
        dim3 grid(H1DIM / GBN, (N_NODES + GBM - 1) / GBM);  // (8, 391)
        gemm_abT<<<grid, 256>>>(aggx, W1, h1, N_NODES, H1DIM, DIM,
                                HEADS * DIM, /*head_span=*/HID / GBN, /*headK=*/DIM,
                                b1, /*elu=*/1);
    }

    // ---- layer 2 ----
    {
        dim3 grid(EMB / GBN, (N_NODES + GBM - 1) / GBM);    // (1, 391)
        gemm_abT<<<grid, 256>>>(h1, W2, hh2, N_NODES, EMB, H1DIM,
                                H1DIM, 0, 0, nullptr, 0);
    }
    alpha2_kernel<<<(N_NODES + 7) / 8, 256>>>(a_src2, a_dst2);
    gather2_kernel<<<(N_NODES + 7) / 8, 256>>>(e0, b2, out);  // writes z into out

    // ---- heads ----
    logits_kernel<<<(N_NODES + 7) / 8, 256>>>(out, cls_W, cls_b, out);
    preds_kernel<<<(2 * P_EDGES + 7) / 8, 256>>>(out, p, nn, out);
}

// round 8
// speedup vs baseline: 3.6306x; 1.7504x over previous
#include <cuda_runtime.h>
#include <cuda_bf16.h>
#include <cstdint>

#define N_NODES 50000
#define DIM     128
#define E_REAL  200000
#define E_TOT   250000   // + self loops
#define P_EDGES 50000
#define HEADS   4
#define HID     256
#define H1DIM   1024     // HEADS*HID
#define EMB     128
#define SLOPE   0.2f

#define Z_ELEMS   ((size_t)N_NODES * EMB)          // 6.4M
#define LOG_OFF   (Z_ELEMS)                        // logits at 6.4M
#define PRED_OFF  (Z_ELEMS + (size_t)N_NODES * 4)  // preds at 6.6M

// ---------------- scratch (device globals; no allocs allowed) ----------------
__device__ float g_aggx[(size_t)N_NODES * HEADS * DIM]; // per-head aggregated x [N,4,128]
__device__ float g_h1  [(size_t)N_NODES * H1DIM];       // layer1 output (post bias+ELU)
__device__ float g_hh2 [(size_t)N_NODES * EMB];         // layer2 features (pre-agg)
__device__ float g_as1 [(size_t)N_NODES * HEADS];
__device__ float g_ad1 [(size_t)N_NODES * HEADS];
__device__ float g_as2 [N_NODES];
__device__ float g_ad2 [N_NODES];
__device__ float g_v1s [HEADS * DIM];   // W1^T a_src1 per head
__device__ float g_v1d [HEADS * DIM];   // W1^T a_dst1 per head

// CSR by destination
__device__ int g_deg[N_NODES];
__device__ int g_off[N_NODES + 1];
__device__ int g_cur[N_NODES];
__device__ int g_eid[E_TOT];

// =================== tf32 tensor-core GEMM: C = A @ B^T =====================
// 128x128 block tile, 8 warps (2x4), warp tile 64x32, mma.m16n8k8.tf32.
// Double-buffered smem, one __syncthreads per k-tile.
// head_span>0: A column window = (blockIdx.x/head_span)*headK (grouped GEMM).
#define TBM 128
#define TBN 128
#define TBK 16
#define TPAD 8

__device__ __forceinline__ uint32_t f2tf(float v) {
    uint32_t r;
    asm("cvt.rna.tf32.f32 %0, %1;" : "=r"(r) : "f"(v));
    return r;
}

__device__ __forceinline__ void mma_tf32(float* c, const uint32_t* a, const uint32_t* b) {
    asm volatile(
        "mma.sync.aligned.m16n8k8.row.col.f32.tf32.tf32.f32 "
        "{%0,%1,%2,%3}, {%4,%5,%6,%7}, {%8,%9}, {%0,%1,%2,%3};\n"
        : "+f"(c[0]), "+f"(c[1]), "+f"(c[2]), "+f"(c[3])
        : "r"(a[0]), "r"(a[1]), "r"(a[2]), "r"(a[3]), "r"(b[0]), "r"(b[1]));
}

__global__ __launch_bounds__(256, 2)
void gemm_tf32(const float* __restrict__ A, const float* __restrict__ B,
               float* __restrict__ C, int M, int N, int K, int lda,
               int head_span, int headK,
               const float* __restrict__ bias, int do_elu) {
    __shared__ uint32_t As[2][TBK][TBM + TPAD];
    __shared__ uint32_t Bs[2][TBK][TBN + TPAD];
    int bm = blockIdx.y * TBM;
    int bn = blockIdx.x * TBN;
    int a_off = head_span ? (blockIdx.x / head_span) * headK : 0;
    int tid = threadIdx.x;
    int warp = tid >> 5, lane = tid & 31;
    int wm = warp >> 2, wn = warp & 3;      // warp grid 2 x 4
    int gid = lane >> 2, t4 = lane & 3;

    float acc[4][4][4];
    #pragma unroll
    for (int i = 0; i < 4; i++)
        #pragma unroll
        for (int j = 0; j < 4; j++)
            #pragma unroll
            for (int c = 0; c < 4; c++) acc[i][j][c] = 0.f;

    float4 ra[2], rb[2];

    auto LOADG = [&](int t) {
        int k0 = t * TBK;
        #pragma unroll
        for (int l = 0; l < 2; l++) {
            int li = tid * 2 + l;           // 0..511
            int r = li >> 2, kq = li & 3;
            int gm = bm + r;
            ra[l] = (gm < M) ? *(const float4*)(A + (size_t)gm * lda + a_off + k0 + kq * 4)
                             : make_float4(0.f, 0.f, 0.f, 0.f);
            int gn = bn + r;
            rb[l] = (gn < N) ? *(const float4*)(B + (size_t)gn * K + k0 + kq * 4)
                             : make_float4(0.f, 0.f, 0.f, 0.f);
        }
    };
    auto STORES = [&](int s) {
        #pragma unroll
        for (int l = 0; l < 2; l++) {
            int li = tid * 2 + l;
            int r = li >> 2, kq = li & 3;
            As[s][kq * 4 + 0][r] = f2tf(ra[l].x);
            As[s][kq * 4 + 1][r] = f2tf(ra[l].y);
            As[s][kq * 4 + 2][r] = f2tf(ra[l].z);
            As[s][kq * 4 + 3][r] = f2tf(ra[l].w);
            Bs[s][kq * 4 + 0][r] = f2tf(rb[l].x);
            Bs[s][kq * 4 + 1][r] = f2tf(rb[l].y);
            Bs[s][kq * 4 + 2][r] = f2tf(rb[l].z);
            Bs[s][kq * 4 + 3][r] = f2tf(rb[l].w);
        }
    };
    auto COMPUTE = [&](int s) {
        #pragma unroll
        for (int kk = 0; kk < TBK; kk += 8) {
            uint32_t af[4][4], bf[4][2];
            #pragma unroll
            for (int i = 0; i < 4; i++) {
                int row = wm * 64 + i * 16 + gid;
                af[i][0] = As[s][kk + t4][row];
                af[i][1] = As[s][kk + t4][row + 8];
                af[i][2] = As[s][kk + t4 + 4][row];
                af[i][3] = As[s][kk + t4 + 4][row + 8];
            }
            #pragma unroll
            for (int j = 0; j < 4; j++) {
                int col = wn * 32 + j * 8 + gid;
                bf[j][0] = Bs[s][kk + t4][col];
                bf[j][1] = Bs[s][kk + t4 + 4][col];
            }
            #pragma unroll
            for (int i = 0; i < 4; i++)
                #pragma unroll
                for (int j = 0; j < 4; j++)
                    mma_tf32(acc[i][j], af[i], bf[j]);
        }
    };

    int nt = K / TBK;
    LOADG(0); STORES(0); __syncthreads();
    for (int t = 0; t < nt; t++) {
        if (t + 1 < nt) LOADG(t + 1);
        COMPUTE(t & 1);
        if (t + 1 < nt) { STORES((t + 1) & 1); __syncthreads(); }
    }

    // epilogue: optional bias + ELU, write fp32
    #pragma unroll
    for (int i = 0; i < 4; i++) {
        int r0 = bm + wm * 64 + i * 16 + gid;
        #pragma unroll
        for (int half = 0; half < 2; half++) {
            int gm = r0 + half * 8;
            if (gm >= M) continue;
            float* row = C + (size_t)gm * N;
            #pragma unroll
            for (int j = 0; j < 4; j++) {
                int gc = bn + wn * 32 + j * 8 + t4 * 2;
                float v0 = acc[i][j][half * 2 + 0];
                float v1 = acc[i][j][half * 2 + 1];
                if (bias) {
                    v0 += bias[gc]; v1 += bias[gc + 1];
                    if (do_elu) {
                        v0 = v0 > 0.f ? v0 : expm1f(v0);
                        v1 = v1 > 0.f ? v1 : expm1f(v1);
                    }
                }
                row[gc] = v0; row[gc + 1] = v1;
            }
        }
    }
}

// ======================= CSR build (by destination) =========================
__global__ void csr_count(const int* __restrict__ e1) {
    int t = blockIdx.x * blockDim.x + threadIdx.x;
    if (t >= E_TOT) return;
    int dst = (t < E_REAL) ? e1[t] : t - E_REAL;
    atomicAdd(&g_deg[dst], 1);
}

__global__ void csr_scan() {
    __shared__ int s[1024];
    const int per = (N_NODES + 1023) / 1024;  // 49
    int tid = threadIdx.x;
    int base = tid * per;
    int sum = 0;
    for (int i = 0; i < per; i++) {
        int idx = base + i;
        if (idx < N_NODES) sum += g_deg[idx];
    }
    s[tid] = sum;
    __syncthreads();
    for (int off = 1; off < 1024; off <<= 1) {
        int v = (tid >= off) ? s[tid - off] : 0;
        __syncthreads();
        s[tid] += v;
        __syncthreads();
    }
    int run = (tid > 0) ? s[tid - 1] : 0;   // exclusive
    for (int i = 0; i < per; i++) {
        int idx = base + i;
        if (idx < N_NODES) {
            g_off[idx] = run;
            g_cur[idx] = run;
            run += g_deg[idx];
        }
    }
    if (tid == 0) g_off[N_NODES] = E_TOT;
}

__global__ void csr_place(const int* __restrict__ e1) {
    int t = blockIdx.x * blockDim.x + threadIdx.x;
    if (t >= E_TOT) return;
    int dst = (t < E_REAL) ? e1[t] : t - E_REAL;
    int pos = atomicAdd(&g_cur[dst], 1);
    g_eid[pos] = t;
}

// ============== v = W1^T a (rank-4 projections), parallel over j-chunks =====
__global__ void proj_v(const float* __restrict__ W1, const float* __restrict__ as,
                       const float* __restrict__ ad) {
    // grid: 64 blocks = set(2) x head(4) x jchunk(8); block = 128 threads (c)
    int b = blockIdx.x;
    int set = b & 1;
    int h = (b >> 1) & 3;
    int jc = b >> 3;
    int c = threadIdx.x;
    const float* a = set ? ad : as;
    float s = 0.f;
    #pragma unroll 8
    for (int j = jc * 32; j < jc * 32 + 32; j++)
        s += a[h * HID + j] * W1[(size_t)(h * HID + j) * DIM + c];
    atomicAdd(&(set ? g_v1d : g_v1s)[h * DIM + c], s);
}

// ============== layer-1 alphas directly from x (warp per node) ==============
__global__ void alpha1x_kernel(const float* __restrict__ x) {
    int node = blockIdx.x * (blockDim.x >> 5) + (threadIdx.x >> 5);
    if (node >= N_NODES) return;
    int lane = threadIdx.x & 31;
    float4 xv = ((const float4*)x)[(size_t)node * 32 + lane];
    float s[HEADS], d[HEADS];
    #pragma unroll
    for (int h = 0; h < HEADS; h++) {
        float4 vs = ((const float4*)g_v1s)[h * 32 + lane];
        float4 vd = ((const float4*)g_v1d)[h * 32 + lane];
        s[h] = xv.x * vs.x + xv.y * vs.y + xv.z * vs.z + xv.w * vs.w;
        d[h] = xv.x * vd.x + xv.y * vd.y + xv.z * vd.z + xv.w * vd.w;
    }
    #pragma unroll
    for (int o = 16; o; o >>= 1) {
        #pragma unroll
        for (int h = 0; h < HEADS; h++) {
            s[h] += __shfl_xor_sync(0xffffffffu, s[h], o);
            d[h] += __shfl_xor_sync(0xffffffffu, d[h], o);
        }
    }
    if (lane == 0) {
        #pragma unroll
        for (int h = 0; h < HEADS; h++) {
            g_as1[node * HEADS + h] = s[h];
            g_ad1[node * HEADS + h] = d[h];
        }
    }
}

// ====== layer-1 gather on x: softmax + per-head weighted agg of x[src] ======
__global__ void gatherx_kernel(const float* __restrict__ x, const int* __restrict__ e0) {
    int node = blockIdx.x * (blockDim.x >> 5) + (threadIdx.x >> 5);
    if (node >= N_NODES) return;
    int lane = threadIdx.x & 31;
    int beg = g_off[node], end = g_off[node + 1];

    float adh = (lane < HEADS) ? g_ad1[node * HEADS + lane] : 0.f;
    float den = 0.f;
    for (int e = beg; e < end; e++) {
        int id = g_eid[e];
        int src = (id < E_REAL) ? e0[id] : node;
        if (lane < HEADS) {
            float ev = g_as1[src * HEADS + lane] + adh;
            ev = ev >= 0.f ? ev : SLOPE * ev;
            den += __expf(ev);
        }
    }
    float inv = 1.f / (den + 1e-16f);

    float4 a0 = make_float4(0.f,0.f,0.f,0.f), a1 = a0, a2 = a0, a3 = a0;
    for (int e = beg; e < end; e++) {
        int id = g_eid[e];
        int src = (id < E_REAL) ? e0[id] : node;
        float w = 0.f;
        if (lane < HEADS) {
            float ev = g_as1[src * HEADS + lane] + adh;
            ev = ev >= 0.f ? ev : SLOPE * ev;
            w = __expf(ev) * inv;
        }
        float w0 = __shfl_sync(0xffffffffu, w, 0);
        float w1 = __shfl_sync(0xffffffffu, w, 1);
        float w2 = __shfl_sync(0xffffffffu, w, 2);
        float w3 = __shfl_sync(0xffffffffu, w, 3);
        float4 v = ((const float4*)x)[(size_t)src * 32 + lane];
        a0.x += w0*v.x; a0.y += w0*v.y; a0.z += w0*v.z; a0.w += w0*v.w;
        a1.x += w1*v.x; a1.y += w1*v.y; a1.z += w1*v.z; a1.w += w1*v.w;
        a2.x += w2*v.x; a2.y += w2*v.y; a2.z += w2*v.z; a2.w += w2*v.w;
        a3.x += w3*v.x; a3.y += w3*v.y; a3.z += w3*v.z; a3.w += w3*v.w;
    }
    float4* dst = (float4*)(g_aggx + (size_t)node * HEADS * DIM);
    dst[0 * 32 + lane] = a0;
    dst[1 * 32 + lane] = a1;
    dst[2 * 32 + lane] = a2;
    dst[3 * 32 + lane] = a3;
}

// ================== per-node attention logits, layer 2 ======================
__global__ void alpha2_kernel(const float* __restrict__ a_src, const float* __restrict__ a_dst) {
    int node = blockIdx.x * (blockDim.x >> 5) + (threadIdx.x >> 5);
    if (node >= N_NODES) return;
    int lane = threadIdx.x & 31;
    float4 v  = ((const float4*)g_hh2)[(size_t)node * 32 + lane];
    float4 vs = ((const float4*)a_src)[lane];
    float4 vd = ((const float4*)a_dst)[lane];
    float s = v.x*vs.x + v.y*vs.y + v.z*vs.z + v.w*vs.w;
    float d = v.x*vd.x + v.y*vd.y + v.z*vd.z + v.w*vd.w;
    #pragma unroll
    for (int o = 16; o; o >>= 1) {
        s += __shfl_xor_sync(0xffffffffu, s, o);
        d += __shfl_xor_sync(0xffffffffu, d, o);
    }
    if (lane == 0) { g_as2[node] = s; g_ad2[node] = d; }
}

// ====== layer-2 gather: softmax + weighted agg + bias + ELU -> z ============
__global__ void gather2_kernel(const int* __restrict__ e0, const float* __restrict__ b2,
                               float* __restrict__ zout) {
    int node = blockIdx.x * (blockDim.x >> 5) + (threadIdx.x >> 5);
    if (node >= N_NODES) return;
    int lane = threadIdx.x & 31;
    int beg = g_off[node], end = g_off[node + 1];
    float adn = g_ad2[node];

    float den = 0.f;
    for (int e = beg; e < end; e++) {
        int id = g_eid[e];
        int src = (id < E_REAL) ? e0[id] : node;
        if (lane == 0) {
            float ev = g_as2[src] + adn;
            ev = ev >= 0.f ? ev : SLOPE * ev;
            den += __expf(ev);
        }
    }
    float inv = 1.f / (den + 1e-16f);

    float4 acc = make_float4(0.f,0.f,0.f,0.f);
    for (int e = beg; e < end; e++) {
        int id = g_eid[e];
        int src = (id < E_REAL) ? e0[id] : node;
        float w = 0.f;
        if (lane == 0) {
            float ev = g_as2[src] + adn;
            ev = ev >= 0.f ? ev : SLOPE * ev;
            w = __expf(ev) * inv;
        }
        w = __shfl_sync(0xffffffffu, w, 0);
        float4 v = ((const float4*)g_hh2)[(size_t)src * 32 + lane];
        acc.x += w*v.x; acc.y += w*v.y; acc.z += w*v.z; acc.w += w*v.w;
    }
    float4 bv = ((const float4*)b2)[lane];
    acc.x += bv.x; acc.y += bv.y; acc.z += bv.z; acc.w += bv.w;
    acc.x = acc.x > 0.f ? acc.x : expm1f(acc.x);
    acc.y = acc.y > 0.f ? acc.y : expm1f(acc.y);
    acc.z = acc.z > 0.f ? acc.z : expm1f(acc.z);
    acc.w = acc.w > 0.f ? acc.w : expm1f(acc.w);
    ((float4*)zout)[(size_t)node * 32 + lane] = acc;
}

// ---------------- classifier logits (warp/node) ----------------
__global__ void logits_kernel(const float* __restrict__ z, const float* __restrict__ cls_W,
                              const float* __restrict__ cls_b, float* __restrict__ out) {
    int node = blockIdx.x * (blockDim.x >> 5) + (threadIdx.x >> 5);
    if (node >= N_NODES) return;
    int lane = threadIdx.x & 31;
    float4 zv = *(const float4*)(z + (size_t)node * EMB + lane * 4);
    float acc[4];
    #pragma unroll
    for (int k = 0; k < 4; k++) {
        float4 wv = *(const float4*)(cls_W + k * EMB + lane * 4);
        acc[k] = zv.x * wv.x + zv.y * wv.y + zv.z * wv.z + zv.w * wv.w;
    }
    #pragma unroll
    for (int k = 0; k < 4; k++)
        #pragma unroll
        for (int o = 16; o; o >>= 1) acc[k] += __shfl_down_sync(0xffffffffu, acc[k], o);
    if (lane == 0) {
        #pragma unroll
        for (int k = 0; k < 4; k++)
            out[LOG_OFF + (size_t)node * 4 + k] = acc[k] + cls_b[k];
    }
}

// ---------------- link predictions (warp/pair) ----------------
__global__ void preds_kernel(const float* __restrict__ z, const int* __restrict__ p,
                             const int* __restrict__ nn, float* __restrict__ out) {
    int pair = blockIdx.x * (blockDim.x >> 5) + (threadIdx.x >> 5);
    if (pair >= 2 * P_EDGES) return;
    int lane = threadIdx.x & 31;
    int a, b;
    if (pair < P_EDGES) { a = p[pair]; b = p[P_EDGES + pair]; }
    else { int j = pair - P_EDGES; a = nn[j]; b = nn[P_EDGES + j]; }
    float4 za = *(const float4*)(z + (size_t)a * EMB + lane * 4);
    float4 zb = *(const float4*)(z + (size_t)b * EMB + lane * 4);
    float s = za.x * zb.x + za.y * zb.y + za.z * zb.z + za.w * zb.w;
    #pragma unroll
    for (int o = 16; o; o >>= 1) s += __shfl_down_sync(0xffffffffu, s, o);
    if (lane == 0) out[PRED_OFF + pair] = 1.f / (1.f + __expf(-s));
}

// ============================================================================
extern "C" void kernel_launch(void* const* d_in, const int* in_sizes, int n_in,
                              void* d_out, int out_size) {
    const float* x      = (const float*)d_in[0];
    const int*   e      = (const int*)  d_in[1];
    const int*   p      = (const int*)  d_in[2];
    const int*   nn     = (const int*)  d_in[3];
    const float* W1     = (const float*)d_in[4];
    const float* a_src1 = (const float*)d_in[5];
    const float* a_dst1 = (const float*)d_in[6];
    const float* b1     = (const float*)d_in[7];
    const float* W2     = (const float*)d_in[8];
    const float* a_src2 = (const float*)d_in[9];
    const float* a_dst2 = (const float*)d_in[10];
    const float* b2     = (const float*)d_in[11];
    const float* cls_W  = (const float*)d_in[12];
    const float* cls_b  = (const float*)d_in[13];
    float* out = (float*)d_out;

    const int* e0 = e;
    const int* e1 = e + E_REAL;

    float *aggx, *h1, *hh2, *v1s, *v1d;
    int* deg;
    cudaGetSymbolAddress((void**)&aggx, g_aggx);
    cudaGetSymbolAddress((void**)&h1,   g_h1);
    cudaGetSymbolAddress((void**)&hh2,  g_hh2);
    cudaGetSymbolAddress((void**)&v1s,  g_v1s);
    cudaGetSymbolAddress((void**)&v1d,  g_v1d);
    cudaGetSymbolAddress((void**)&deg,  g_deg);

    // ---- CSR build (by destination) + alpha projections ----
    cudaMemsetAsync(deg, 0, N_NODES * sizeof(int));
    cudaMemsetAsync(v1s, 0, HEADS * DIM * sizeof(float));
    cudaMemsetAsync(v1d, 0, HEADS * DIM * sizeof(float));
    csr_count<<<(E_TOT + 255) / 256, 256>>>(e1);
    csr_scan<<<1, 1024>>>();
    csr_place<<<(E_TOT + 255) / 256, 256>>>(e1);

    proj_v<<<64, 128>>>(W1, a_src1, a_dst1);
    alpha1x_kernel<<<(N_NODES + 7) / 8, 256>>>(x);

    // ---- layer 1: aggregate x per head, then grouped tf32 GEMM + bias+ELU ----
    gatherx_kernel<<<(N_NODES + 7) / 8, 256>>>(x, e0);
    {
        dim3 grid(H1DIM / TBN, (N_NODES + TBM - 1) / TBM);  // (8, 391)
        gemm_tf32<<<grid, 256>>>(aggx, W1, h1, N_NODES, H1DIM, DIM,
                                 HEADS * DIM, /*head_span=*/HID / TBN, /*headK=*/DIM,
                                 b1, /*elu=*/1);
    }

    // ---- layer 2 ----
    {
        dim3 grid(EMB / TBN, (N_NODES + TBM - 1) / TBM);    // (1, 391)
        gemm_tf32<<<grid, 256>>>(h1, W2, hh2, N_NODES, EMB, H1DIM,
                                 H1DIM, 0, 0, nullptr, 0);
    }
    alpha2_kernel<<<(N_NODES + 7) / 8, 256>>>(a_src2, a_dst2);
    gather2_kernel<<<(N_NODES + 7) / 8, 256>>>(e0, b2, out);  // writes z into out

    // ---- heads ----
    logits_kernel<<<(N_NODES + 7) / 8, 256>>>(out, cls_W, cls_b, out);
    preds_kernel<<<(2 * P_EDGES + 7) / 8, 256>>>(out, p, nn, out);
}

// round 11
// speedup vs baseline: 3.7775x; 1.0405x over previous
#include <cuda_runtime.h>
#include <cuda_bf16.h>
#include <cstdint>

#define N_NODES 50000
#define DIM     128
#define E_REAL  200000
#define E_TOT   250000   // + self loops
#define P_EDGES 50000
#define HEADS   4
#define HID     256
#define H1DIM   1024     // HEADS*HID
#define EMB     128
#define SLOPE   0.2f

#define Z_ELEMS   ((size_t)N_NODES * EMB)          // 6.4M
#define LOG_OFF   (Z_ELEMS)                        // logits at 6.4M
#define PRED_OFF  (Z_ELEMS + (size_t)N_NODES * 4)  // preds at 6.6M

// ---------------- scratch (device globals; no allocs allowed) ----------------
__device__ float g_aggx[(size_t)N_NODES * HEADS * DIM]; // per-head aggregated x [N,4,128]
__device__ float g_h1  [(size_t)N_NODES * H1DIM];       // layer1 output (post bias+ELU)
__device__ float g_hh2 [(size_t)N_NODES * EMB];         // layer2 features (pre-agg)
__device__ float g_as1 [(size_t)N_NODES * HEADS];
__device__ float g_ad1 [(size_t)N_NODES * HEADS];
__device__ float g_as2 [N_NODES];
__device__ float g_ad2 [N_NODES];
__device__ float g_v1s [HEADS * DIM];   // W1^T a_src1 per head
__device__ float g_v1d [HEADS * DIM];   // W1^T a_dst1 per head

// CSR by destination (stores SOURCE node ids directly — no edge-id indirection)
__device__ int g_deg[N_NODES];
__device__ int g_off[N_NODES + 1];
__device__ int g_cur[N_NODES];
__device__ int g_src[E_TOT];

// =================== tf32 tensor-core GEMM: C = A @ B^T =====================
#define TBM 128
#define TBN 128
#define TBK 16
#define TPAD 8

__device__ __forceinline__ uint32_t f2tf(float v) {
    uint32_t r;
    asm("cvt.rna.tf32.f32 %0, %1;" : "=r"(r) : "f"(v));
    return r;
}

__device__ __forceinline__ void mma_tf32(float* c, const uint32_t* a, const uint32_t* b) {
    asm volatile(
        "mma.sync.aligned.m16n8k8.row.col.f32.tf32.tf32.f32 "
        "{%0,%1,%2,%3}, {%4,%5,%6,%7}, {%8,%9}, {%0,%1,%2,%3};\n"
        : "+f"(c[0]), "+f"(c[1]), "+f"(c[2]), "+f"(c[3])
        : "r"(a[0]), "r"(a[1]), "r"(a[2]), "r"(a[3]), "r"(b[0]), "r"(b[1]));
}

__global__ __launch_bounds__(256, 2)
void gemm_tf32(const float* __restrict__ A, const float* __restrict__ B,
               float* __restrict__ C, int M, int N, int K, int lda,
               int head_span, int headK,
               const float* __restrict__ bias, int do_elu) {
    __shared__ uint32_t As[2][TBK][TBM + TPAD];
    __shared__ uint32_t Bs[2][TBK][TBN + TPAD];
    int bm = blockIdx.y * TBM;
    int bn = blockIdx.x * TBN;
    int a_off = head_span ? (blockIdx.x / head_span) * headK : 0;
    int tid = threadIdx.x;
    int warp = tid >> 5, lane = tid & 31;
    int wm = warp >> 2, wn = warp & 3;      // warp grid 2 x 4
    int gid = lane >> 2, t4 = lane & 3;

    float acc[4][4][4];
    #pragma unroll
    for (int i = 0; i < 4; i++)
        #pragma unroll
        for (int j = 0; j < 4; j++)
            #pragma unroll
            for (int c = 0; c < 4; c++) acc[i][j][c] = 0.f;

    float4 ra[2], rb[2];

    auto LOADG = [&](int t) {
        int k0 = t * TBK;
        #pragma unroll
        for (int l = 0; l < 2; l++) {
            int li = tid * 2 + l;           // 0..511
            int r = li >> 2, kq = li & 3;
            int gm = bm + r;
            ra[l] = (gm < M) ? *(const float4*)(A + (size_t)gm * lda + a_off + k0 + kq * 4)
                             : make_float4(0.f, 0.f, 0.f, 0.f);
            int gn = bn + r;
            rb[l] = (gn < N) ? *(const float4*)(B + (size_t)gn * K + k0 + kq * 4)
                             : make_float4(0.f, 0.f, 0.f, 0.f);
        }
    };
    auto STORES = [&](int s) {
        #pragma unroll
        for (int l = 0; l < 2; l++) {
            int li = tid * 2 + l;
            int r = li >> 2, kq = li & 3;
            As[s][kq * 4 + 0][r] = f2tf(ra[l].x);
            As[s][kq * 4 + 1][r] = f2tf(ra[l].y);
            As[s][kq * 4 + 2][r] = f2tf(ra[l].z);
            As[s][kq * 4 + 3][r] = f2tf(ra[l].w);
            Bs[s][kq * 4 + 0][r] = f2tf(rb[l].x);
            Bs[s][kq * 4 + 1][r] = f2tf(rb[l].y);
            Bs[s][kq * 4 + 2][r] = f2tf(rb[l].z);
            Bs[s][kq * 4 + 3][r] = f2tf(rb[l].w);
        }
    };
    auto COMPUTE = [&](int s) {
        #pragma unroll
        for (int kk = 0; kk < TBK; kk += 8) {
            uint32_t af[4][4], bf[4][2];
            #pragma unroll
            for (int i = 0; i < 4; i++) {
                int row = wm * 64 + i * 16 + gid;
                af[i][0] = As[s][kk + t4][row];
                af[i][1] = As[s][kk + t4][row + 8];
                af[i][2] = As[s][kk + t4 + 4][row];
                af[i][3] = As[s][kk + t4 + 4][row + 8];
            }
            #pragma unroll
            for (int j = 0; j < 4; j++) {
                int col = wn * 32 + j * 8 + gid;
                bf[j][0] = Bs[s][kk + t4][col];
                bf[j][1] = Bs[s][kk + t4 + 4][col];
            }
            #pragma unroll
            for (int i = 0; i < 4; i++)
                #pragma unroll
                for (int j = 0; j < 4; j++)
                    mma_tf32(acc[i][j], af[i], bf[j]);
        }
    };

    int nt = K / TBK;
    LOADG(0); STORES(0); __syncthreads();
    for (int t = 0; t < nt; t++) {
        if (t + 1 < nt) LOADG(t + 1);
        COMPUTE(t & 1);
        if (t + 1 < nt) { STORES((t + 1) & 1); __syncthreads(); }
    }

    #pragma unroll
    for (int i = 0; i < 4; i++) {
        int r0 = bm + wm * 64 + i * 16 + gid;
        #pragma unroll
        for (int half = 0; half < 2; half++) {
            int gm = r0 + half * 8;
            if (gm >= M) continue;
            float* row = C + (size_t)gm * N;
            #pragma unroll
            for (int j = 0; j < 4; j++) {
                int gc = bn + wn * 32 + j * 8 + t4 * 2;
                float v0 = acc[i][j][half * 2 + 0];
                float v1 = acc[i][j][half * 2 + 1];
                if (bias) {
                    v0 += bias[gc]; v1 += bias[gc + 1];
                    if (do_elu) {
                        v0 = v0 > 0.f ? v0 : expm1f(v0);
                        v1 = v1 > 0.f ? v1 : expm1f(v1);
                    }
                }
                row[gc] = v0; row[gc + 1] = v1;
            }
        }
    }
}

// ======================= CSR build (by destination) =========================
__global__ void csr_count(const int* __restrict__ e1) {
    int t = blockIdx.x * blockDim.x + threadIdx.x;
    if (t >= E_TOT) return;
    int dst = (t < E_REAL) ? e1[t] : t - E_REAL;
    atomicAdd(&g_deg[dst], 1);
}

__global__ void csr_scan() {
    __shared__ int s[1024];
    const int per = (N_NODES + 1023) / 1024;  // 49
    int tid = threadIdx.x;
    int base = tid * per;
    int sum = 0;
    for (int i = 0; i < per; i++) {
        int idx = base + i;
        if (idx < N_NODES) sum += g_deg[idx];
    }
    s[tid] = sum;
    __syncthreads();
    for (int off = 1; off < 1024; off <<= 1) {
        int v = (tid >= off) ? s[tid - off] : 0;
        __syncthreads();
        s[tid] += v;
        __syncthreads();
    }
    int run = (tid > 0) ? s[tid - 1] : 0;   // exclusive
    for (int i = 0; i < per; i++) {
        int idx = base + i;
        if (idx < N_NODES) {
            g_off[idx] = run;
            g_cur[idx] = run;
            run += g_deg[idx];
        }
    }
    if (tid == 0) g_off[N_NODES] = E_TOT;
}

// stores SOURCE node directly (kills the eid->e0 dependent-load chain)
__global__ void csr_place(const int* __restrict__ e0, const int* __restrict__ e1) {
    int t = blockIdx.x * blockDim.x + threadIdx.x;
    if (t >= E_TOT) return;
    int src, dst;
    if (t < E_REAL) { src = e0[t]; dst = e1[t]; }
    else { src = dst = t - E_REAL; }
    int pos = atomicAdd(&g_cur[dst], 1);
    g_src[pos] = src;
}

// ============== v = W1^T a (rank-4 projections), parallel over j-chunks =====
__global__ void proj_v(const float* __restrict__ W1, const float* __restrict__ as,
                       const float* __restrict__ ad) {
    int b = blockIdx.x;
    int set = b & 1;
    int h = (b >> 1) & 3;
    int jc = b >> 3;
    int c = threadIdx.x;
    const float* a = set ? ad : as;
    float s = 0.f;
    #pragma unroll 8
    for (int j = jc * 32; j < jc * 32 + 32; j++)
        s += a[h * HID + j] * W1[(size_t)(h * HID + j) * DIM + c];
    atomicAdd(&(set ? g_v1d : g_v1s)[h * DIM + c], s);
}

// ============== layer-1 alphas directly from x (warp per node) ==============
__global__ void alpha1x_kernel(const float* __restrict__ x) {
    int node = blockIdx.x * (blockDim.x >> 5) + (threadIdx.x >> 5);
    if (node >= N_NODES) return;
    int lane = threadIdx.x & 31;
    float4 xv = ((const float4*)x)[(size_t)node * 32 + lane];
    float s[HEADS], d[HEADS];
    #pragma unroll
    for (int h = 0; h < HEADS; h++) {
        float4 vs = ((const float4*)g_v1s)[h * 32 + lane];
        float4 vd = ((const float4*)g_v1d)[h * 32 + lane];
        s[h] = xv.x * vs.x + xv.y * vs.y + xv.z * vs.z + xv.w * vs.w;
        d[h] = xv.x * vd.x + xv.y * vd.y + xv.z * vd.z + xv.w * vd.w;
    }
    #pragma unroll
    for (int o = 16; o; o >>= 1) {
        #pragma unroll
        for (int h = 0; h < HEADS; h++) {
            s[h] += __shfl_xor_sync(0xffffffffu, s[h], o);
            d[h] += __shfl_xor_sync(0xffffffffu, d[h], o);
        }
    }
    if (lane == 0) {
        #pragma unroll
        for (int h = 0; h < HEADS; h++) {
            g_as1[node * HEADS + h] = s[h];
            g_ad1[node * HEADS + h] = d[h];
        }
    }
}

// ====== layer-1 gather: SINGLE-PASS unnormalized agg + den, scale at end ====
// warp per destination node; lane owns one float4 of the 128-dim x row.
__global__ void gatherx_kernel(const float* __restrict__ x) {
    int node = blockIdx.x * (blockDim.x >> 5) + (threadIdx.x >> 5);
    if (node >= N_NODES) return;
    int lane = threadIdx.x & 31;
    int beg = g_off[node], end = g_off[node + 1];

    float adh = (lane < HEADS) ? g_ad1[node * HEADS + lane] : 0.f;
    float den = 0.f;
    float4 a0 = make_float4(0.f,0.f,0.f,0.f), a1 = a0, a2 = a0, a3 = a0;

    for (int e = beg; e < end; e++) {
        int src = g_src[e];
        float w = 0.f;
        if (lane < HEADS) {
            float ev = g_as1[src * HEADS + lane] + adh;
            ev = ev >= 0.f ? ev : SLOPE * ev;
            w = __expf(ev);
            den += w;
        }
        float w0 = __shfl_sync(0xffffffffu, w, 0);
        float w1 = __shfl_sync(0xffffffffu, w, 1);
        float w2 = __shfl_sync(0xffffffffu, w, 2);
        float w3 = __shfl_sync(0xffffffffu, w, 3);
        float4 v = ((const float4*)x)[(size_t)src * 32 + lane];
        a0.x += w0*v.x; a0.y += w0*v.y; a0.z += w0*v.z; a0.w += w0*v.w;
        a1.x += w1*v.x; a1.y += w1*v.y; a1.z += w1*v.z; a1.w += w1*v.w;
        a2.x += w2*v.x; a2.y += w2*v.y; a2.z += w2*v.z; a2.w += w2*v.w;
        a3.x += w3*v.x; a3.y += w3*v.y; a3.z += w3*v.z; a3.w += w3*v.w;
    }
    float inv = (lane < HEADS) ? 1.f / (den + 1e-16f) : 0.f;
    float i0 = __shfl_sync(0xffffffffu, inv, 0);
    float i1 = __shfl_sync(0xffffffffu, inv, 1);
    float i2 = __shfl_sync(0xffffffffu, inv, 2);
    float i3 = __shfl_sync(0xffffffffu, inv, 3);
    a0.x *= i0; a0.y *= i0; a0.z *= i0; a0.w *= i0;
    a1.x *= i1; a1.y *= i1; a1.z *= i1; a1.w *= i1;
    a2.x *= i2; a2.y *= i2; a2.z *= i2; a2.w *= i2;
    a3.x *= i3; a3.y *= i3; a3.z *= i3; a3.w *= i3;

    float4* dst = (float4*)(g_aggx + (size_t)node * HEADS * DIM);
    dst[0 * 32 + lane] = a0;
    dst[1 * 32 + lane] = a1;
    dst[2 * 32 + lane] = a2;
    dst[3 * 32 + lane] = a3;
}

// ================== per-node attention logits, layer 2 ======================
__global__ void alpha2_kernel(const float* __restrict__ a_src, const float* __restrict__ a_dst) {
    int node = blockIdx.x * (blockDim.x >> 5) + (threadIdx.x >> 5);
    if (node >= N_NODES) return;
    int lane = threadIdx.x & 31;
    float4 v  = ((const float4*)g_hh2)[(size_t)node * 32 + lane];
    float4 vs = ((const float4*)a_src)[lane];
    float4 vd = ((const float4*)a_dst)[lane];
    float s = v.x*vs.x + v.y*vs.y + v.z*vs.z + v.w*vs.w;
    float d = v.x*vd.x + v.y*vd.y + v.z*vd.z + v.w*vd.w;
    #pragma unroll
    for (int o = 16; o; o >>= 1) {
        s += __shfl_xor_sync(0xffffffffu, s, o);
        d += __shfl_xor_sync(0xffffffffu, d, o);
    }
    if (lane == 0) { g_as2[node] = s; g_ad2[node] = d; }
}

// == layer-2 gather: SINGLE-PASS agg + bias + ELU -> z, FUSED cls logits =====
// warp per destination node; lane owns one float4 of the 128-dim row.
__global__ void gather2_kernel(const float* __restrict__ b2,
                               const float* __restrict__ cls_W,
                               const float* __restrict__ cls_b,
                               float* __restrict__ out) {
    int node = blockIdx.x * (blockDim.x >> 5) + (threadIdx.x >> 5);
    if (node >= N_NODES) return;
    int lane = threadIdx.x & 31;
    int beg = g_off[node], end = g_off[node + 1];
    float adn = g_ad2[node];

    float den = 0.f;
    float4 acc = make_float4(0.f,0.f,0.f,0.f);
    for (int e = beg; e < end; e++) {
        int src = g_src[e];
        float w = 0.f;
        if (lane == 0) {
            float ev = g_as2[src] + adn;
            ev = ev >= 0.f ? ev : SLOPE * ev;
            w = __expf(ev);
            den += w;
        }
        w = __shfl_sync(0xffffffffu, w, 0);
        float4 v = ((const float4*)g_hh2)[(size_t)src * 32 + lane];
        acc.x += w*v.x; acc.y += w*v.y; acc.z += w*v.z; acc.w += w*v.w;
    }
    float inv = 1.f / (den + 1e-16f);
    inv = __shfl_sync(0xffffffffu, inv, 0);
    float4 bv = ((const float4*)b2)[lane];
    acc.x = acc.x * inv + bv.x;
    acc.y = acc.y * inv + bv.y;
    acc.z = acc.z * inv + bv.z;
    acc.w = acc.w * inv + bv.w;
    acc.x = acc.x > 0.f ? acc.x : expm1f(acc.x);
    acc.y = acc.y > 0.f ? acc.y : expm1f(acc.y);
    acc.z = acc.z > 0.f ? acc.z : expm1f(acc.z);
    acc.w = acc.w > 0.f ? acc.w : expm1f(acc.w);
    ((float4*)out)[(size_t)node * 32 + lane] = acc;

    // fused classifier logits: z row is register-resident across the warp
    float lg[4];
    #pragma unroll
    for (int k = 0; k < 4; k++) {
        float4 wv = ((const float4*)cls_W)[k * 32 + lane];
        lg[k] = acc.x * wv.x + acc.y * wv.y + acc.z * wv.z + acc.w * wv.w;
        #pragma unroll
        for (int o = 16; o; o >>= 1) lg[k] += __shfl_xor_sync(0xffffffffu, lg[k], o);
    }
    if (lane == 0) {
        #pragma unroll
        for (int k = 0; k < 4; k++)
            out[LOG_OFF + (size_t)node * 4 + k] = lg[k] + cls_b[k];
    }
}

// ---------------- link predictions (warp/pair) ----------------
__global__ void preds_kernel(const float* __restrict__ z, const int* __restrict__ p,
                             const int* __restrict__ nn, float* __restrict__ out) {
    int pair = blockIdx.x * (blockDim.x >> 5) + (threadIdx.x >> 5);
    if (pair >= 2 * P_EDGES) return;
    int lane = threadIdx.x & 31;
    int a, b;
    if (pair < P_EDGES) { a = p[pair]; b = p[P_EDGES + pair]; }
    else { int j = pair - P_EDGES; a = nn[j]; b = nn[P_EDGES + j]; }
    float4 za = *(const float4*)(z + (size_t)a * EMB + lane * 4);
    float4 zb = *(const float4*)(z + (size_t)b * EMB + lane * 4);
    float s = za.x * zb.x + za.y * zb.y + za.z * zb.z + za.w * zb.w;
    #pragma unroll
    for (int o = 16; o; o >>= 1) s += __shfl_down_sync(0xffffffffu, s, o);
    if (lane == 0) out[PRED_OFF + pair] = 1.f / (1.f + __expf(-s));
}

// ============================================================================
extern "C" void kernel_launch(void* const* d_in, const int* in_sizes, int n_in,
                              void* d_out, int out_size) {
    const float* x      = (const float*)d_in[0];
    const int*   e      = (const int*)  d_in[1];
    const int*   p      = (const int*)  d_in[2];
    const int*   nn     = (const int*)  d_in[3];
    const float* W1     = (const float*)d_in[4];
    const float* a_src1 = (const float*)d_in[5];
    const float* a_dst1 = (const float*)d_in[6];
    const float* b1     = (const float*)d_in[7];
    const float* W2     = (const float*)d_in[8];
    const float* a_src2 = (const float*)d_in[9];
    const float* a_dst2 = (const float*)d_in[10];
    const float* b2     = (const float*)d_in[11];
    const float* cls_W  = (const float*)d_in[12];
    const float* cls_b  = (const float*)d_in[13];
    float* out = (float*)d_out;

    const int* e0 = e;
    const int* e1 = e + E_REAL;

    float *aggx, *h1, *hh2, *v1s, *v1d;
    int* deg;
    cudaGetSymbolAddress((void**)&aggx, g_aggx);
    cudaGetSymbolAddress((void**)&h1,   g_h1);
    cudaGetSymbolAddress((void**)&hh2,  g_hh2);
    cudaGetSymbolAddress((void**)&v1s,  g_v1s);
    cudaGetSymbolAddress((void**)&v1d,  g_v1d);
    cudaGetSymbolAddress((void**)&deg,  g_deg);

    // ---- CSR build (by destination) + alpha projections ----
    cudaMemsetAsync(deg, 0, N_NODES * sizeof(int));
    cudaMemsetAsync(v1s, 0, HEADS * DIM * sizeof(float));
    cudaMemsetAsync(v1d, 0, HEADS * DIM * sizeof(float));
    csr_count<<<(E_TOT + 255) / 256, 256>>>(e1);
    csr_scan<<<1, 1024>>>();
    csr_place<<<(E_TOT + 255) / 256, 256>>>(e0, e1);

    proj_v<<<64, 128>>>(W1, a_src1, a_dst1);
    alpha1x_kernel<<<(N_NODES + 7) / 8, 256>>>(x);

    // ---- layer 1: aggregate x per head, then grouped tf32 GEMM + bias+ELU ----
    gatherx_kernel<<<(N_NODES + 7) / 8, 256>>>(x);
    {
        dim3 grid(H1DIM / TBN, (N_NODES + TBM - 1) / TBM);  // (8, 391)
        gemm_tf32<<<grid, 256>>>(aggx, W1, h1, N_NODES, H1DIM, DIM,
                                 HEADS * DIM, /*head_span=*/HID / TBN, /*headK=*/DIM,
                                 b1, /*elu=*/1);
    }

    // ---- layer 2 ----
    {
        dim3 grid(EMB / TBN, (N_NODES + TBM - 1) / TBM);    // (1, 391)
        gemm_tf32<<<grid, 256>>>(h1, W2, hh2, N_NODES, EMB, H1DIM,
                                 H1DIM, 0, 0, nullptr, 0);
    }
    alpha2_kernel<<<(N_NODES + 7) / 8, 256>>>(a_src2, a_dst2);
    gather2_kernel<<<(N_NODES + 7) / 8, 256>>>(b2, cls_W, cls_b, out);  // z + logits

    // ---- link predictions ----
    preds_kernel<<<(2 * P_EDGES + 7) / 8, 256>>>(out, p, nn, out);
}